// round 8
// baseline (speedup 1.0000x reference)
#include <cuda_runtime.h>
#include <stdint.h>

#define D 8
#define DD 64
#define MAX_N 1024
#define REG_CELLS 512                 // cells per region (128 KB of output)
#define NREG ((MAX_N * MAX_N) / REG_CELLS)   // 2048
#define REG_CAP 96                    // max edges per region (avg 16)

__device__ int g_cnt[NREG];
__device__ int g_list[NREG * REG_CAP];

__global__ void clear_counts() {
    int i = blockIdx.x * blockDim.x + threadIdx.x;
    if (i < NREG) g_cnt[i] = 0;
}

__global__ void bin_edges(const int* __restrict__ ei, int e, int n) {
    int idx = blockIdx.x * blockDim.x + threadIdx.x;
    if (idx >= e) return;
    int cell = ei[idx] * n + ei[e + idx];
    int region = cell / REG_CELLS;
    int pos = atomicAdd(&g_cnt[region], 1);
    if (pos < REG_CAP) g_list[region * REG_CAP + pos] = idx;
}

// One block owns one 512-cell region: pure-STG zero fill of 128 KB, barrier,
// then overwrite the region's edge cells. Only this block writes this region,
// so the barrier fully orders zero-then-edge stores. Duplicate (src,dst)
// edges produce identical values -> order within the list is irrelevant.
__global__ void __launch_bounds__(256) fill_kernel(
        const float* __restrict__ x,
        const int* __restrict__ ei,
        const float* __restrict__ W,
        float4* __restrict__ out4,
        int e, int n) {
    int t = threadIdx.x;
    int q = t & 15;

    // W rows 4q..4q+3 in registers (broadcast L1 loads, once per thread).
    float4 w[8];
    #pragma unroll
    for (int c = 0; c < 4; c++) {
        const float4* wp = (const float4*)(W + (q * 4 + c) * D);
        w[2 * c]     = __ldg(wp);
        w[2 * c + 1] = __ldg(wp + 1);
    }

    // (a) zero this block's region: 512 cells * 16 float4 = 8192 float4.
    size_t base4 = (size_t)blockIdx.x * (REG_CELLS * 16);
    const float4 z = make_float4(0.f, 0.f, 0.f, 0.f);
    #pragma unroll
    for (int k = 0; k < (REG_CELLS * 16) / 256; k++)
        out4[base4 + k * 256 + t] = z;

    __syncthreads();

    // (b) overwrite edge cells inside this region.
    int cnt = g_cnt[blockIdx.x];
    if (cnt > REG_CAP) cnt = REG_CAP;
    for (int j = t >> 4; j < cnt; j += 16) {
        int edge = g_list[blockIdx.x * REG_CAP + j];
        int src = __ldg(&ei[edge]);
        int dst = __ldg(&ei[e + edge]);

        const float4* xs = (const float4*)(x + src * D);
        const float4* xd = (const float4*)(x + dst * D);
        float4 a0 = __ldg(xs), a1 = __ldg(xs + 1);
        float4 b0 = __ldg(xd), b1 = __ldg(xd + 1);

        float dv[D];
        dv[0] = fabsf(a0.x - b0.x); dv[1] = fabsf(a0.y - b0.y);
        dv[2] = fabsf(a0.z - b0.z); dv[3] = fabsf(a0.w - b0.w);
        dv[4] = fabsf(a1.x - b1.x); dv[5] = fabsf(a1.y - b1.y);
        dv[6] = fabsf(a1.z - b1.z); dv[7] = fabsf(a1.w - b1.w);

        float acc[4];
        #pragma unroll
        for (int c = 0; c < 4; c++) {
            acc[c] = w[2*c].x   * dv[0] + w[2*c].y   * dv[1]
                   + w[2*c].z   * dv[2] + w[2*c].w   * dv[3]
                   + w[2*c+1].x * dv[4] + w[2*c+1].y * dv[5]
                   + w[2*c+1].z * dv[6] + w[2*c+1].w * dv[7];
        }

        size_t cell = (size_t)src * n + dst;
        out4[cell * 16 + q] = make_float4(acc[0], acc[1], acc[2], acc[3]);
    }
}

extern "C" void kernel_launch(void* const* d_in, const int* in_sizes, int n_in,
                              void* d_out, int out_size) {
    const float* x  = (const float*)d_in[0];
    const int*   ei = (const int*)d_in[1];    // int64 in reference, int32 here
    const float* W  = (const float*)d_in[2];

    int n = in_sizes[0] / D;     // 1024
    int e = in_sizes[1] / 2;     // 32768
    int nreg = (n * n) / REG_CELLS;

    clear_counts<<<(NREG + 255) / 256, 256>>>();
    bin_edges<<<(e + 255) / 256, 256>>>(ei, e, n);
    fill_kernel<<<nreg, 256>>>(x, ei, W, (float4*)d_out, e, n);
}